// round 4
// baseline (speedup 1.0000x reference)
#include <cuda_runtime.h>
#include <cuda_bf16.h>
#include <math.h>
#include <stdint.h>

#define BB 8
#define SS 4096
#define DD 256
#define HH 64
#define RT (BB*SS)
#define TQ 64          // q rows per CTA
#define TK 128         // k keys per tile
#define CAP 64         // candidate buffer per row

// ---------------- scratch ----------------
__device__ float g_Qf[RT*HH];
__device__ float g_Kf[RT*HH];
__device__ float g_Vf[RT*HH];
__device__ float g_gate[BB*HH];

// monotone float<->uint key for atomicMax over floats
__device__ __forceinline__ unsigned fkey(float f) {
    unsigned u = __float_as_uint(f);
    return u ^ ((unsigned)((int)u >> 31) | 0x80000000u);
}
__device__ __forceinline__ float funkey(unsigned u) {
    u ^= (u & 0x80000000u) ? 0x80000000u : 0xffffffffu;
    return __uint_as_float(u);
}

#define PACK2(dst, x) asm("mov.b64 %0, {%1, %1};" : "=l"(dst) : "r"(__float_as_uint(x)))
#define FMA2(acc, a, b) asm("fma.rn.f32x2 %0, %1, %2, %0;" : "+l"(acc) : "l"(a), "l"(b))
#define UNPACK2(lo, hi, v) asm("mov.b64 {%0, %1}, %2;" : "=r"(lo), "=r"(hi) : "l"(v))

// ---------------- kernel 1: fused QKV GEMM (fp32) ----------------
__global__ __launch_bounds__(192) void qkv_kernel(
    const float* __restrict__ x, const float* __restrict__ Wq,
    const float* __restrict__ Wk, const float* __restrict__ Wv)
{
    __shared__ float xs[16][DD];
    int row0 = blockIdx.x * 16;
    int tid = threadIdx.x;
    for (int idx = tid; idx < 16*DD; idx += 192) {
        int r = idx >> 8, k = idx & 255;
        xs[r][k] = x[(size_t)(row0 + r)*DD + k];
    }
    __syncthreads();

    int m = tid >> 6;
    int h = tid & 63;
    const float* W = (m == 0) ? Wq : (m == 1) ? Wk : Wv;
    float* O = (m == 0) ? g_Qf : (m == 1) ? g_Kf : g_Vf;

    float acc[16];
    #pragma unroll
    for (int r = 0; r < 16; r++) acc[r] = 0.f;

    #pragma unroll 2
    for (int k = 0; k < DD; k += 4) {
        float w0 = W[(k+0)*HH + h];
        float w1 = W[(k+1)*HH + h];
        float w2 = W[(k+2)*HH + h];
        float w3 = W[(k+3)*HH + h];
        #pragma unroll
        for (int r = 0; r < 16; r++) {
            const float4 a = *(const float4*)&xs[r][k];
            acc[r] = fmaf(a.x, w0, fmaf(a.y, w1, fmaf(a.z, w2, fmaf(a.w, w3, acc[r]))));
        }
    }
    #pragma unroll
    for (int r = 0; r < 16; r++)
        O[(size_t)(row0 + r)*HH + h] = acc[r];
}

// ---------------- kernel 2: gate ----------------
__global__ __launch_bounds__(128) void gate_kernel() {
    int b = blockIdx.x >> 6;
    int h = blockIdx.x & 63;
    float s = 0.f;
    for (int i = threadIdx.x; i < SS; i += 128)
        s += g_Qf[((size_t)b*SS + i)*HH + h];
    __shared__ float red[128];
    red[threadIdx.x] = s;
    __syncthreads();
    for (int off = 64; off; off >>= 1) {
        if (threadIdx.x < off) red[threadIdx.x] += red[threadIdx.x + off];
        __syncthreads();
    }
    if (threadIdx.x == 0)
        g_gate[blockIdx.x] = 1.f / (1.f + expf(-red[0] * (1.f / (float)SS)));
}

// ---------------- kernel 3: fused exact attention ----------------
// smem: Qs[64][68] | Ks[64][132] | cand_t[64*CAP] | cand_idx[64*CAP](u16)
//       | cnt[64] | mkey[64] | so[8][64]
#define SM_QS     0
#define SM_KS     (64*68)
#define SM_CT     (SM_KS + 64*132)
#define SM_CI_B   ((SM_CT + 64*CAP)*4)                 // byte offset
#define SM_CNT_B  (SM_CI_B + 64*CAP*2)
#define SM_MK_B   (SM_CNT_B + 64*4)
#define SM_SO_B   (SM_MK_B + 64*4)
#define SM_TOTAL  (SM_SO_B + 8*64*4)

__global__ __launch_bounds__(256) void attn_kernel(float* __restrict__ out) {
    extern __shared__ __align__(16) char sm[];
    float* Qs = (float*)sm;                          // [d][68]
    float* Ks = (float*)sm + SM_KS;                  // [d][132]
    float* cand_t = (float*)sm + SM_CT;              // [64*CAP]
    unsigned short* cand_idx = (unsigned short*)(sm + SM_CI_B);
    unsigned* cnt  = (unsigned*)(sm + SM_CNT_B);
    unsigned* mkey = (unsigned*)(sm + SM_MK_B);
    float* so = (float*)(sm + SM_SO_B);              // [8][64]

    int tid = threadIdx.x;
    int b  = blockIdx.x >> 6;
    int q0 = (blockIdx.x & 63) * TQ;

    if (tid < 64) { cnt[tid] = 0u; mkey[tid] = 0u; }

    // load Q tile transposed: g_Qf[(b*SS+q0+row)*64+d] -> Qs[d*68+row]
    for (int c = tid; c < TQ*16; c += 256) {
        int row = c >> 4, d4 = (c & 15) * 4;
        float4 v = *(const float4*)&g_Qf[((size_t)b*SS + q0 + row)*HH + d4];
        Qs[(d4+0)*68+row] = v.x; Qs[(d4+1)*68+row] = v.y;
        Qs[(d4+2)*68+row] = v.z; Qs[(d4+3)*68+row] = v.w;
    }
    __syncthreads();

    int ti = tid & 15;     // q group: rows ti*4..+3
    int tj = tid >> 4;     // k group: keys tj*8..+7
    float rm[4] = {-3e38f, -3e38f, -3e38f, -3e38f};

    for (int kt = 0; kt < SS/TK; kt++) {
        int k0 = kt * TK;
        // load K tile transposed
        for (int c = tid; c < TK*16; c += 256) {
            int key = c >> 4, d4 = (c & 15) * 4;
            float4 v = *(const float4*)&g_Kf[((size_t)b*SS + k0 + key)*HH + d4];
            Ks[(d4+0)*132+key] = v.x; Ks[(d4+1)*132+key] = v.y;
            Ks[(d4+2)*132+key] = v.z; Ks[(d4+3)*132+key] = v.w;
        }
        __syncthreads();

        unsigned long long acc[4][4];
        #pragma unroll
        for (int r = 0; r < 4; r++)
            #pragma unroll
            for (int p = 0; p < 4; p++) acc[r][p] = 0ull;

        #pragma unroll 8
        for (int d = 0; d < HH; d++) {
            const float4 q4 = *(const float4*)&Qs[d*68 + ti*4];
            const ulonglong2 kA = *(const ulonglong2*)&Ks[d*132 + tj*8];
            const ulonglong2 kB = *(const ulonglong2*)&Ks[d*132 + tj*8 + 4];
            unsigned long long qp;
            PACK2(qp, q4.x);
            FMA2(acc[0][0], kA.x, qp); FMA2(acc[0][1], kA.y, qp);
            FMA2(acc[0][2], kB.x, qp); FMA2(acc[0][3], kB.y, qp);
            PACK2(qp, q4.y);
            FMA2(acc[1][0], kA.x, qp); FMA2(acc[1][1], kA.y, qp);
            FMA2(acc[1][2], kB.x, qp); FMA2(acc[1][3], kB.y, qp);
            PACK2(qp, q4.z);
            FMA2(acc[2][0], kA.x, qp); FMA2(acc[2][1], kA.y, qp);
            FMA2(acc[2][2], kB.x, qp); FMA2(acc[2][3], kB.y, qp);
            PACK2(qp, q4.w);
            FMA2(acc[3][0], kA.x, qp); FMA2(acc[3][1], kA.y, qp);
            FMA2(acc[3][2], kB.x, qp); FMA2(acc[3][3], kB.y, qp);
        }

        // screen: celu + candidate insertion (no exp in hot path)
        #pragma unroll
        for (int r = 0; r < 4; r++) {
            int row = ti*4 + r;
            #pragma unroll
            for (int p = 0; p < 4; p++) {
                unsigned u0, u1;
                UNPACK2(u0, u1, acc[r][p]);
                #pragma unroll
                for (int e = 0; e < 2; e++) {
                    float s = __uint_as_float(e ? u1 : u0) * 0.125f;
                    bool neg = (s <= 0.f);
                    if (neg && rm[r] > 19.f) continue;   // weight < e^-20 provably
                    float t = neg ? expm1f(s) : s;       // exact CELU
                    if (t > rm[r]) rm[r] = t;
                    if (t > rm[r] - 20.f) {
                        unsigned slot = atomicAdd(&cnt[row], 1u);
                        if (slot < CAP) {
                            cand_t[row*CAP + slot] = t;
                            cand_idx[row*CAP + slot] = (unsigned short)(k0 + tj*8 + p*2 + e);
                        }
                    }
                }
            }
        }
        // periodic cross-thread max sharing (tightens screen, lag-safe)
        if ((kt & 3) == 3) {
            #pragma unroll
            for (int r = 0; r < 4; r++) atomicMax(&mkey[ti*4 + r], fkey(rm[r]));
        }
        if ((kt & 3) == 0 && kt) {
            #pragma unroll
            for (int r = 0; r < 4; r++) {
                float g = funkey(mkey[ti*4 + r]);
                if (g > rm[r]) rm[r] = g;
            }
        }
        __syncthreads();
    }

    // final exact max flush
    #pragma unroll
    for (int r = 0; r < 4; r++) atomicMax(&mkey[ti*4 + r], fkey(rm[r]));
    __syncthreads();

    // -------- finalize: warp per 8 rows --------
    int warp = tid >> 5, lane = tid & 31;
    for (int rr = 0; rr < 8; rr++) {
        int row = warp*8 + rr;
        unsigned c = cnt[row];
        float M = funkey(mkey[row]);
        float l = 0.f;
        float2 o = make_float2(0.f, 0.f);

        if (c <= CAP) {
            #pragma unroll 4
            for (unsigned k = 0; k < c; k++) {
                float t = cand_t[row*CAP + k];
                float w = __expf(t - M);
                int idx = cand_idx[row*CAP + k];
                float2 v = *(const float2*)&g_Vf[((size_t)b*SS + idx)*HH + lane*2];
                l += w;
                o.x += w * v.x;
                o.y += w * v.y;
            }
        } else {
            // ---- exact full-row rescan (degenerate rows only) ----
            float fm = -3e38f, fl = 0.f;
            for (int k = lane; k < SS; k += 32) {
                const float* Kr = &g_Kf[((size_t)b*SS + k)*HH];
                float s = 0.f;
                #pragma unroll 16
                for (int d = 0; d < HH; d++) s = fmaf(Qs[d*68 + row], Kr[d], s);
                s *= 0.125f;
                float t = (s > 0.f) ? s : expm1f(s);
                float mn = fmaxf(fm, t);
                fl = fl*__expf(fm - mn) + __expf(t - mn);
                fm = mn;
            }
            #pragma unroll
            for (int off = 16; off; off >>= 1) {
                float om = __shfl_xor_sync(0xffffffffu, fm, off);
                float ol = __shfl_xor_sync(0xffffffffu, fl, off);
                float mn = fmaxf(fm, om);
                fl = fl*__expf(fm - mn) + ol*__expf(om - mn);
                fm = mn;
            }
            so[warp*64 + lane] = 0.f;
            so[warp*64 + lane + 32] = 0.f;
            __syncwarp();
            for (int k = lane; k < SS; k += 32) {
                const float* Kr = &g_Kf[((size_t)b*SS + k)*HH];
                float s = 0.f;
                #pragma unroll 16
                for (int d = 0; d < HH; d++) s = fmaf(Qs[d*68 + row], Kr[d], s);
                s *= 0.125f;
                float t = (s > 0.f) ? s : expm1f(s);
                if (t > fm - 20.f) {
                    float w = __expf(t - fm);
                    const float* Vr = &g_Vf[((size_t)b*SS + k)*HH];
                    for (int h = 0; h < HH; h++)
                        atomicAdd(&so[warp*64 + h], w * Vr[h]);
                }
            }
            __syncwarp();
            l = fl;
            o.x = so[warp*64 + lane*2];
            o.y = so[warp*64 + lane*2 + 1];
        }

        float inv = (l > 0.f) ? (1.f / l) : 0.f;
        float2 gt = *(const float2*)&g_gate[b*HH + lane*2];
        float2 res = make_float2(o.x*inv*gt.x, o.y*inv*gt.y);
        *(float2*)&out[((size_t)b*SS + q0 + row)*HH + lane*2] = res;
    }
}

// ---------------- launch ----------------
extern "C" void kernel_launch(void* const* d_in, const int* in_sizes, int n_in,
                              void* d_out, int out_size) {
    int xi = 0;
    for (int i = 0; i < 4; i++) if (in_sizes[i] == BB*SS*DD) { xi = i; break; }
    const float* ptrs[3];
    int w = 0;
    for (int i = 0; i < 4; i++) if (i != xi) ptrs[w++] = (const float*)d_in[i];
    const float* x  = (const float*)d_in[xi];
    const float* Wq = ptrs[0];
    const float* Wk = ptrs[1];
    const float* Wv = ptrs[2];
    float* out = (float*)d_out;

    cudaFuncSetAttribute(attn_kernel, cudaFuncAttributeMaxDynamicSharedMemorySize, SM_TOTAL);

    qkv_kernel<<<RT/16, 192>>>(x, Wq, Wk, Wv);
    gate_kernel<<<BB*HH, 128>>>();
    attn_kernel<<<BB*(SS/TQ), 256, SM_TOTAL>>>(out);
}

// round 6
// speedup vs baseline: 63.3592x; 63.3592x over previous
#include <cuda_runtime.h>
#include <math.h>
#include <stdint.h>

#define BB 8
#define SS 4096
#define DD 256
#define HH 64
#define RT (BB*SS)
#define TQ 64          // q rows per CTA
#define TK 256         // keys per tile
#define NT (SS/TK)     // 16 tiles
#define CAP 32

// ---------------- scratch ----------------
__device__ float g_Qf[RT*HH];
__device__ float g_Kf[RT*HH];
__device__ float g_Vf[RT*HH];
__device__ float g_gate[BB*HH];

__device__ __forceinline__ unsigned fkey(float f) {
    unsigned u = __float_as_uint(f);
    return u ^ ((unsigned)((int)u >> 31) | 0x80000000u);
}
__device__ __forceinline__ float funkey(unsigned u) {
    u ^= (u & 0x80000000u) ? 0x80000000u : 0xffffffffu;
    return __uint_as_float(u);
}

#define PACK2(dst, x) asm("mov.b64 %0, {%1, %1};" : "=l"(dst) : "r"(__float_as_uint(x)))
#define FMA2(acc, a, b) asm("fma.rn.f32x2 %0, %1, %2, %0;" : "+l"(acc) : "l"(a), "l"(b))
#define UNPACK2(lo, hi, v) asm("mov.b64 {%0, %1}, %2;" : "=r"(lo), "=r"(hi) : "l"(v))

// ---------------- kernel 1: fused QKV GEMM ----------------
__global__ __launch_bounds__(192) void qkv_kernel(
    const float* __restrict__ x, const float* __restrict__ Wq,
    const float* __restrict__ Wk, const float* __restrict__ Wv)
{
    __shared__ float xs[32][DD];
    int row0 = blockIdx.x * 32;
    int tid = threadIdx.x;
    for (int idx = tid; idx < 32*DD; idx += 192) {
        int r = idx >> 8, k = idx & 255;
        xs[r][k] = x[(size_t)(row0 + r)*DD + k];
    }
    __syncthreads();

    int m = tid >> 6;
    int h = tid & 63;
    const float* W = (m == 0) ? Wq : (m == 1) ? Wk : Wv;
    float* O = (m == 0) ? g_Qf : (m == 1) ? g_Kf : g_Vf;

    float acc[32];
    #pragma unroll
    for (int r = 0; r < 32; r++) acc[r] = 0.f;

    #pragma unroll 4
    for (int k = 0; k < DD; k += 2) {
        float w0 = W[(k+0)*HH + h];
        float w1 = W[(k+1)*HH + h];
        #pragma unroll
        for (int r = 0; r < 32; r++) {
            float2 a = *(const float2*)&xs[r][k];
            acc[r] = fmaf(a.x, w0, fmaf(a.y, w1, acc[r]));
        }
    }
    #pragma unroll
    for (int r = 0; r < 32; r++)
        O[(size_t)(row0 + r)*HH + h] = acc[r];
}

// ---------------- kernel 2: gate ----------------
__global__ __launch_bounds__(128) void gate_kernel() {
    int b = blockIdx.x >> 6;
    int h = blockIdx.x & 63;
    float s = 0.f;
    for (int i = threadIdx.x; i < SS; i += 128)
        s += g_Qf[((size_t)b*SS + i)*HH + h];
    __shared__ float red[128];
    red[threadIdx.x] = s;
    __syncthreads();
    for (int off = 64; off; off >>= 1) {
        if (threadIdx.x < off) red[threadIdx.x] += red[threadIdx.x + off];
        __syncthreads();
    }
    if (threadIdx.x == 0)
        g_gate[blockIdx.x] = 1.f / (1.f + expf(-red[0] * (1.f / (float)SS)));
}

// ---------------- kernel 3: two-sweep exact attention ----------------
struct __align__(16) Smem {
    float Qs[64*68];            // [d][row(+pad)]
    float Ks[64*260];           // [d][key(+pad)]
    unsigned rowtile[64*NT];    // per-(row,tile) max key (pre-scale s)
    unsigned thrkey[64];
    float thrpre[64];
    float cand_t[64*CAP];
    unsigned short cand_idx[64*CAP];
    unsigned cnt[64];
    int list[64];
    int nlist;
    int pad_;
    float so[8*64];             // fallback PV accumulators
};

__global__ __launch_bounds__(256, 2) void attn_kernel(float* __restrict__ out) {
    extern __shared__ Smem smem[];
    Smem& S = smem[0];

    int tid = threadIdx.x;
    int b  = blockIdx.x >> 6;
    int q0 = (blockIdx.x & 63) * TQ;

    // init rowtile
    for (int i = tid; i < 64*NT; i += 256) S.rowtile[i] = 0u;

    // load Q tile transposed: thread loads quarter-row (16 floats)
    {
        int row = tid >> 2, qtr = (tid & 3) * 16;
        const float* Qr = &g_Qf[((size_t)b*SS + q0 + row)*HH + qtr];
        #pragma unroll
        for (int d4 = 0; d4 < 16; d4 += 4) {
            float4 v = *(const float4*)&Qr[d4];
            S.Qs[(qtr+d4+0)*68+row] = v.x; S.Qs[(qtr+d4+1)*68+row] = v.y;
            S.Qs[(qtr+d4+2)*68+row] = v.z; S.Qs[(qtr+d4+3)*68+row] = v.w;
        }
    }

    int ti = tid & 7;      // rowgroup: rows ti*8..+7
    int tj = tid >> 3;     // keygroup: keys tj*8..+7 (0..31)

    // ================= sweep 1: full GEMM, per-(row,tile) max only =================
    for (int kt = 0; kt < NT; kt++) {
        __syncthreads();
        // load K tile transposed: thread = one key row
        {
            const float* Kr = &g_Kf[((size_t)b*SS + kt*TK + tid)*HH];
            #pragma unroll
            for (int d4 = 0; d4 < HH; d4 += 4) {
                float4 v = *(const float4*)&Kr[d4];
                S.Ks[(d4+0)*260+tid] = v.x; S.Ks[(d4+1)*260+tid] = v.y;
                S.Ks[(d4+2)*260+tid] = v.z; S.Ks[(d4+3)*260+tid] = v.w;
            }
        }
        __syncthreads();

        unsigned long long acc[8][4];
        #pragma unroll
        for (int r = 0; r < 8; r++)
            #pragma unroll
            for (int p = 0; p < 4; p++) acc[r][p] = 0ull;

        #pragma unroll 8
        for (int d = 0; d < HH; d++) {
            const ulonglong2 kA = *(const ulonglong2*)&S.Ks[d*260 + tj*8];
            const ulonglong2 kB = *(const ulonglong2*)&S.Ks[d*260 + tj*8 + 4];
            const float4 qa = *(const float4*)&S.Qs[d*68 + ti*8];
            const float4 qb = *(const float4*)&S.Qs[d*68 + ti*8 + 4];
            unsigned long long qp;
            PACK2(qp, qa.x);
            FMA2(acc[0][0], kA.x, qp); FMA2(acc[0][1], kA.y, qp);
            FMA2(acc[0][2], kB.x, qp); FMA2(acc[0][3], kB.y, qp);
            PACK2(qp, qa.y);
            FMA2(acc[1][0], kA.x, qp); FMA2(acc[1][1], kA.y, qp);
            FMA2(acc[1][2], kB.x, qp); FMA2(acc[1][3], kB.y, qp);
            PACK2(qp, qa.z);
            FMA2(acc[2][0], kA.x, qp); FMA2(acc[2][1], kA.y, qp);
            FMA2(acc[2][2], kB.x, qp); FMA2(acc[2][3], kB.y, qp);
            PACK2(qp, qa.w);
            FMA2(acc[3][0], kA.x, qp); FMA2(acc[3][1], kA.y, qp);
            FMA2(acc[3][2], kB.x, qp); FMA2(acc[3][3], kB.y, qp);
            PACK2(qp, qb.x);
            FMA2(acc[4][0], kA.x, qp); FMA2(acc[4][1], kA.y, qp);
            FMA2(acc[4][2], kB.x, qp); FMA2(acc[4][3], kB.y, qp);
            PACK2(qp, qb.y);
            FMA2(acc[5][0], kA.x, qp); FMA2(acc[5][1], kA.y, qp);
            FMA2(acc[5][2], kB.x, qp); FMA2(acc[5][3], kB.y, qp);
            PACK2(qp, qb.z);
            FMA2(acc[6][0], kA.x, qp); FMA2(acc[6][1], kA.y, qp);
            FMA2(acc[6][2], kB.x, qp); FMA2(acc[6][3], kB.y, qp);
            PACK2(qp, qb.w);
            FMA2(acc[7][0], kA.x, qp); FMA2(acc[7][1], kA.y, qp);
            FMA2(acc[7][2], kB.x, qp); FMA2(acc[7][3], kB.y, qp);
        }

        // per-row local max over 8 keys -> rowtile atomicMax (pre-scale s space)
        #pragma unroll
        for (int r = 0; r < 8; r++) {
            float mx = -3e38f;
            #pragma unroll
            for (int p = 0; p < 4; p++) {
                unsigned u0, u1;
                UNPACK2(u0, u1, acc[r][p]);
                mx = fmaxf(mx, fmaxf(__uint_as_float(u0), __uint_as_float(u1)));
            }
            atomicMax(&S.rowtile[(ti*8 + r)*NT + kt], fkey(mx));
        }
    }
    __syncthreads();

    // exact per-row max + thresholds
    if (tid < 64) {
        unsigned mk = 0u;
        #pragma unroll
        for (int t = 0; t < NT; t++) mk = max(mk, S.rowtile[tid*NT + t]);
        float Mpre = funkey(mk);
        float thr = Mpre - 160.f;            // 20 in post-scale space
        S.thrpre[tid] = thr;
        S.thrkey[tid] = fkey(thr);
        // if row max (post-scale) < 20, s-space screen is unsound -> force exact fallback
        S.cnt[tid] = (Mpre < 160.f) ? (CAP + 1000u) : 0u;
    }
    __syncthreads();

    // ================= sweep 2: targeted recompute on qualifying (row, tile) =================
    for (int kt = 0; kt < NT; kt++) {
        if (tid == 0) S.nlist = 0;
        __syncthreads();
        if (tid < 64 && S.rowtile[tid*NT + kt] > S.thrkey[tid])
            S.list[atomicAdd(&S.nlist, 1)] = tid;
        __syncthreads();
        int n = S.nlist;
        if (n == 0) continue;

        // reload this K tile
        {
            const float* Kr = &g_Kf[((size_t)b*SS + kt*TK + tid)*HH];
            #pragma unroll
            for (int d4 = 0; d4 < HH; d4 += 4) {
                float4 v = *(const float4*)&Kr[d4];
                S.Ks[(d4+0)*260+tid] = v.x; S.Ks[(d4+1)*260+tid] = v.y;
                S.Ks[(d4+2)*260+tid] = v.z; S.Ks[(d4+3)*260+tid] = v.w;
            }
        }
        __syncthreads();

        for (int j = 0; j < n; j++) {
            int row = S.list[j];
            float s0 = 0.f, s1 = 0.f, s2 = 0.f, s3 = 0.f;
            #pragma unroll 4
            for (int d = 0; d < HH; d += 4) {
                s0 = fmaf(S.Qs[(d+0)*68 + row], S.Ks[(d+0)*260 + tid], s0);
                s1 = fmaf(S.Qs[(d+1)*68 + row], S.Ks[(d+1)*260 + tid], s1);
                s2 = fmaf(S.Qs[(d+2)*68 + row], S.Ks[(d+2)*260 + tid], s2);
                s3 = fmaf(S.Qs[(d+3)*68 + row], S.Ks[(d+3)*260 + tid], s3);
            }
            float spre = (s0 + s1) + (s2 + s3);
            if (spre > S.thrpre[row]) {
                float sc = spre * 0.125f;
                float t = (sc > 0.f) ? sc : expm1f(sc);   // exact CELU
                unsigned slot = atomicAdd(&S.cnt[row], 1u);
                if (slot < CAP) {
                    S.cand_t[row*CAP + slot] = t;
                    S.cand_idx[row*CAP + slot] = (unsigned short)(kt*TK + tid);
                }
            }
        }
        __syncthreads();
    }

    // ================= epilogue: softmax over candidates + PV + gate =================
    int warp = tid >> 5, lane = tid & 31;
    for (int rr = 0; rr < 8; rr++) {
        int row = warp*8 + rr;
        unsigned c = S.cnt[row];
        float l = 0.f;
        float2 o = make_float2(0.f, 0.f);

        if (c <= CAP) {
            float M = -3e38f;
            for (unsigned k = 0; k < c; k++) M = fmaxf(M, S.cand_t[row*CAP + k]);
            for (unsigned k = 0; k < c; k++) {
                float w = __expf(S.cand_t[row*CAP + k] - M);
                int idx = S.cand_idx[row*CAP + k];
                float2 v = *(const float2*)&g_Vf[((size_t)b*SS + idx)*HH + lane*2];
                l += w;
                o.x += w * v.x;
                o.y += w * v.y;
            }
        } else {
            // ---- exact full-row fallback (essentially never taken) ----
            float fm = -3e38f, fl = 0.f;
            for (int k = lane; k < SS; k += 32) {
                const float* Kr = &g_Kf[((size_t)b*SS + k)*HH];
                float s = 0.f;
                #pragma unroll 16
                for (int d = 0; d < HH; d++) s = fmaf(S.Qs[d*68 + row], Kr[d], s);
                s *= 0.125f;
                float t = (s > 0.f) ? s : expm1f(s);
                float mn = fmaxf(fm, t);
                fl = fl*__expf(fm - mn) + __expf(t - mn);
                fm = mn;
            }
            #pragma unroll
            for (int off = 16; off; off >>= 1) {
                float om = __shfl_xor_sync(0xffffffffu, fm, off);
                float ol = __shfl_xor_sync(0xffffffffu, fl, off);
                float mn = fmaxf(fm, om);
                fl = fl*__expf(fm - mn) + ol*__expf(om - mn);
                fm = mn;
            }
            S.so[warp*64 + lane] = 0.f;
            S.so[warp*64 + lane + 32] = 0.f;
            __syncwarp();
            for (int k = lane; k < SS; k += 32) {
                const float* Kr = &g_Kf[((size_t)b*SS + k)*HH];
                float s = 0.f;
                #pragma unroll 16
                for (int d = 0; d < HH; d++) s = fmaf(S.Qs[d*68 + row], Kr[d], s);
                s *= 0.125f;
                float t = (s > 0.f) ? s : expm1f(s);
                if (t > fm - 20.f) {
                    float w = __expf(t - fm);
                    const float* Vr = &g_Vf[((size_t)b*SS + k)*HH];
                    for (int h = 0; h < HH; h++)
                        atomicAdd(&S.so[warp*64 + h], w * Vr[h]);
                }
            }
            __syncwarp();
            l = fl;
            o.x = S.so[warp*64 + lane*2];
            o.y = S.so[warp*64 + lane*2 + 1];
        }

        float inv = (l > 0.f) ? (1.f / l) : 0.f;
        float2 gt = *(const float2*)&g_gate[b*HH + lane*2];
        float2 res = make_float2(o.x*inv*gt.x, o.y*inv*gt.y);
        *(float2*)&out[((size_t)b*SS + q0 + row)*HH + lane*2] = res;
    }
}

// ---------------- launch ----------------
extern "C" void kernel_launch(void* const* d_in, const int* in_sizes, int n_in,
                              void* d_out, int out_size) {
    int xi = 0;
    for (int i = 0; i < 4; i++) if (in_sizes[i] == BB*SS*DD) { xi = i; break; }
    const float* ptrs[3];
    int w = 0;
    for (int i = 0; i < 4; i++) if (i != xi) ptrs[w++] = (const float*)d_in[i];
    const float* x  = (const float*)d_in[xi];
    const float* Wq = ptrs[0];
    const float* Wk = ptrs[1];
    const float* Wv = ptrs[2];
    float* out = (float*)d_out;

    cudaFuncSetAttribute(attn_kernel, cudaFuncAttributeMaxDynamicSharedMemorySize,
                         (int)sizeof(Smem));

    qkv_kernel<<<RT/32, 192>>>(x, Wq, Wk, Wv);
    gate_kernel<<<BB*HH, 128>>>();
    attn_kernel<<<BB*(SS/TQ), 256, sizeof(Smem)>>>(out);
}

// round 7
// speedup vs baseline: 113.3262x; 1.7886x over previous
#include <cuda_runtime.h>
#include <cuda_bf16.h>
#include <math.h>
#include <stdint.h>

#define BB 8
#define SS 4096
#define DD 256
#define HH 64
#define RT (BB*SS)
#define TQ 64          // q rows per CTA
#define TK 256         // keys per tile
#define NT (SS/TK)     // 16 tiles
#define CAP 32

// ---------------- scratch ----------------
__device__ float g_Qf[RT*HH];
__device__ float g_Kf[RT*HH];
__device__ float g_Vf[RT*HH];
__device__ float g_gate[BB*HH];

__device__ __forceinline__ unsigned fkey(float f) {
    unsigned u = __float_as_uint(f);
    return u ^ ((unsigned)((int)u >> 31) | 0x80000000u);
}
__device__ __forceinline__ float funkey(unsigned u) {
    u ^= (u & 0x80000000u) ? 0x80000000u : 0xffffffffu;
    return __uint_as_float(u);
}

#define PACK2(dst, x) asm("mov.b64 %0, {%1, %1};" : "=l"(dst) : "r"(__float_as_uint(x)))
#define FMA2(acc, a, b) asm("fma.rn.f32x2 %0, %1, %2, %0;" : "+l"(acc) : "l"(a), "l"(b))
#define UNPACK2(lo, hi, v) asm("mov.b64 {%0, %1}, %2;" : "=r"(lo), "=r"(hi) : "l"(v))

// ---------------- kernel 1: fused QKV GEMM (fp32, FMA2) ----------------
__global__ __launch_bounds__(192) void qkv_kernel(
    const float* __restrict__ x, const float* __restrict__ Wq,
    const float* __restrict__ Wk, const float* __restrict__ Wv)
{
    __shared__ __align__(16) float xt[DD*34];   // [k][row(32)+pad]
    int row0 = blockIdx.x * 32;
    int tid = threadIdx.x;

    // fill transposed: r = idx&31, k4 = (idx>>5)*4
    for (int idx = tid; idx < 2048; idx += 192) {
        int r = idx & 31, k4 = (idx >> 5) << 2;
        float4 v = *(const float4*)&x[(size_t)(row0 + r)*DD + k4];
        xt[(k4+0)*34 + r] = v.x;
        xt[(k4+1)*34 + r] = v.y;
        xt[(k4+2)*34 + r] = v.z;
        xt[(k4+3)*34 + r] = v.w;
    }
    __syncthreads();

    int m = tid >> 6;
    int h = tid & 63;
    const float* W = (m == 0) ? Wq : (m == 1) ? Wk : Wv;
    float* O = (m == 0) ? g_Qf : (m == 1) ? g_Kf : g_Vf;

    unsigned long long acc2[16];
    #pragma unroll
    for (int p = 0; p < 16; p++) acc2[p] = 0ull;

    #pragma unroll 4
    for (int k = 0; k < DD; k++) {
        float w = W[k*HH + h];
        unsigned long long wp;
        PACK2(wp, w);
        const unsigned long long* xr = (const unsigned long long*)&xt[k*34];
        #pragma unroll
        for (int p = 0; p < 16; p++)
            FMA2(acc2[p], xr[p], wp);
    }
    #pragma unroll
    for (int p = 0; p < 16; p++) {
        unsigned lo, hi;
        UNPACK2(lo, hi, acc2[p]);
        O[(size_t)(row0 + 2*p    )*HH + h] = __uint_as_float(lo);
        O[(size_t)(row0 + 2*p + 1)*HH + h] = __uint_as_float(hi);
    }
}

// ---------------- kernel 2: gate ----------------
__global__ __launch_bounds__(128) void gate_kernel() {
    int b = blockIdx.x >> 6;
    int h = blockIdx.x & 63;
    float s = 0.f;
    for (int i = threadIdx.x; i < SS; i += 128)
        s += g_Qf[((size_t)b*SS + i)*HH + h];
    __shared__ float red[128];
    red[threadIdx.x] = s;
    __syncthreads();
    for (int off = 64; off; off >>= 1) {
        if (threadIdx.x < off) red[threadIdx.x] += red[threadIdx.x + off];
        __syncthreads();
    }
    if (threadIdx.x == 0)
        g_gate[blockIdx.x] = 1.f / (1.f + expf(-red[0] * (1.f / (float)SS)));
}

// ---------------- kernel 3: two-sweep attention (bf16 mma screen + exact fp32) --------
struct __align__(16) Smem {
    float Qs[64*68];                 // fp32 Q [d][row] (sweep2 + fallback)
    __nv_bfloat16 Qb[64*72];         // bf16 Q [row][d]
    __nv_bfloat16 Kb[256*72];        // bf16 K [key][d] (sweep1 tile)
    unsigned rowtile[64*NT];         // per-(row,tile) bf16 max (pre-scale, fkey)
    float Mpre[64];
    float thrpre[64];                // include threshold (Mpre-200)
    unsigned thrkey[64];             // tile-qualify key (fkey(Mpre-240))
    float cand_t[64*CAP];
    unsigned short cand_idx[64*CAP];
    unsigned cnt[64];
    int list[64];
    int nlist;
    int pad_;
    float so[8*64];
};

__global__ __launch_bounds__(256, 2) void attn_kernel(float* __restrict__ out) {
    extern __shared__ Smem smem[];
    Smem& S = smem[0];

    int tid = threadIdx.x;
    int b  = blockIdx.x >> 6;
    int q0 = (blockIdx.x & 63) * TQ;

    for (int i = tid; i < 64*NT; i += 256) S.rowtile[i] = 0u;

    // load Q: fp32 transposed + bf16 row-major
    {
        int row = tid >> 2, qt = (tid & 3) * 16;
        const float* Qr = &g_Qf[((size_t)b*SS + q0 + row)*HH + qt];
        #pragma unroll
        for (int d4 = 0; d4 < 16; d4 += 4) {
            float4 v = *(const float4*)&Qr[d4];
            S.Qs[(qt+d4+0)*68+row] = v.x; S.Qs[(qt+d4+1)*68+row] = v.y;
            S.Qs[(qt+d4+2)*68+row] = v.z; S.Qs[(qt+d4+3)*68+row] = v.w;
            __nv_bfloat162 p0 = __floats2bfloat162_rn(v.x, v.y);
            __nv_bfloat162 p1 = __floats2bfloat162_rn(v.z, v.w);
            *(__nv_bfloat162*)&S.Qb[row*72 + qt + d4]     = p0;
            *(__nv_bfloat162*)&S.Qb[row*72 + qt + d4 + 2] = p1;
        }
    }

    int warp = tid >> 5, lane = tid & 31;
    int g = lane >> 2, tg = lane & 3;
    int wm = warp >> 1, wn = warp & 1;   // warp tile: rows wm*16..+15, keys wn*128..+127

    // ================= sweep 1: bf16 mma, per-(row,tile) max only =================
    for (int kt = 0; kt < NT; kt++) {
        __syncthreads();
        {   // load K tile -> bf16 smem; thread = one key
            const float* Kr = &g_Kf[((size_t)b*SS + kt*TK + tid)*HH];
            __nv_bfloat16* kb = &S.Kb[tid*72];
            #pragma unroll
            for (int d4 = 0; d4 < HH; d4 += 8) {
                float4 v0 = *(const float4*)&Kr[d4];
                float4 v1 = *(const float4*)&Kr[d4+4];
                __nv_bfloat162 h0 = __floats2bfloat162_rn(v0.x, v0.y);
                __nv_bfloat162 h1 = __floats2bfloat162_rn(v0.z, v0.w);
                __nv_bfloat162 h2 = __floats2bfloat162_rn(v1.x, v1.y);
                __nv_bfloat162 h3 = __floats2bfloat162_rn(v1.z, v1.w);
                uint4 pk;
                pk.x = *(unsigned*)&h0; pk.y = *(unsigned*)&h1;
                pk.z = *(unsigned*)&h2; pk.w = *(unsigned*)&h3;
                *(uint4*)&kb[d4] = pk;
            }
        }
        __syncthreads();

        float acc[16][4];
        #pragma unroll
        for (int ni = 0; ni < 16; ni++)
            #pragma unroll
            for (int e = 0; e < 4; e++) acc[ni][e] = 0.f;

        #pragma unroll
        for (int kk = 0; kk < 64; kk += 16) {
            int r = wm*16 + g;
            uint32_t a0 = *(const uint32_t*)&S.Qb[r*72     + kk + tg*2];
            uint32_t a1 = *(const uint32_t*)&S.Qb[(r+8)*72 + kk + tg*2];
            uint32_t a2 = *(const uint32_t*)&S.Qb[r*72     + kk + tg*2 + 8];
            uint32_t a3 = *(const uint32_t*)&S.Qb[(r+8)*72 + kk + tg*2 + 8];
            #pragma unroll
            for (int ni = 0; ni < 16; ni++) {
                int key = wn*128 + ni*8 + g;
                uint32_t b0 = *(const uint32_t*)&S.Kb[key*72 + kk + tg*2];
                uint32_t b1 = *(const uint32_t*)&S.Kb[key*72 + kk + 8 + tg*2];
                asm volatile(
                    "mma.sync.aligned.m16n8k16.row.col.f32.bf16.bf16.f32 "
                    "{%0,%1,%2,%3}, {%4,%5,%6,%7}, {%8,%9}, {%0,%1,%2,%3};"
                    : "+f"(acc[ni][0]), "+f"(acc[ni][1]),
                      "+f"(acc[ni][2]), "+f"(acc[ni][3])
                    : "r"(a0), "r"(a1), "r"(a2), "r"(a3), "r"(b0), "r"(b1));
            }
        }

        // per-row max (rows wm*16+g and +8), reduce over tg lanes, record
        float m0 = -3e38f, m1 = -3e38f;
        #pragma unroll
        for (int ni = 0; ni < 16; ni++) {
            m0 = fmaxf(m0, fmaxf(acc[ni][0], acc[ni][1]));
            m1 = fmaxf(m1, fmaxf(acc[ni][2], acc[ni][3]));
        }
        m0 = fmaxf(m0, __shfl_xor_sync(0xffffffffu, m0, 1));
        m0 = fmaxf(m0, __shfl_xor_sync(0xffffffffu, m0, 2));
        m1 = fmaxf(m1, __shfl_xor_sync(0xffffffffu, m1, 1));
        m1 = fmaxf(m1, __shfl_xor_sync(0xffffffffu, m1, 2));
        if (tg == 0) {
            atomicMax(&S.rowtile[(wm*16 + g    )*NT + kt], fkey(m0));
            atomicMax(&S.rowtile[(wm*16 + g + 8)*NT + kt], fkey(m1));
        }
    }
    __syncthreads();

    // thresholds (margins cover bf16-mma error ~±30 pre-scale)
    if (tid < 64) {
        unsigned mk = 0u;
        #pragma unroll
        for (int t = 0; t < NT; t++) mk = max(mk, S.rowtile[tid*NT + t]);
        float Mp = funkey(mk);
        S.Mpre[tid]   = Mp;
        S.thrpre[tid] = Mp - 200.f;
        S.thrkey[tid] = fkey(Mp - 240.f);
        S.cnt[tid] = (Mp < 240.f) ? (CAP + 1000u) : 0u;   // degenerate -> exact fallback
    }
    __syncthreads();

    // ================= sweep 2: exact fp32 recompute on qualifying tiles =================
    for (int kt = 0; kt < NT; kt++) {
        if (tid == 0) S.nlist = 0;
        __syncthreads();
        if (tid < 64 && S.rowtile[tid*NT + kt] > S.thrkey[tid])
            S.list[atomicAdd(&S.nlist, 1)] = tid;
        __syncthreads();
        int n = S.nlist;
        if (n > 0) {
            // this thread's K row in registers
            float4 kr[16];
            const float* Kr = &g_Kf[((size_t)b*SS + kt*TK + tid)*HH];
            #pragma unroll
            for (int i = 0; i < 16; i++) kr[i] = *(const float4*)&Kr[i*4];
            for (int j = 0; j < n; j++) {
                int row = S.list[j];
                float s0 = 0.f, s1 = 0.f, s2 = 0.f, s3 = 0.f;
                #pragma unroll
                for (int i = 0; i < 16; i++) {
                    s0 = fmaf(S.Qs[(i*4+0)*68 + row], kr[i].x, s0);
                    s1 = fmaf(S.Qs[(i*4+1)*68 + row], kr[i].y, s1);
                    s2 = fmaf(S.Qs[(i*4+2)*68 + row], kr[i].z, s2);
                    s3 = fmaf(S.Qs[(i*4+3)*68 + row], kr[i].w, s3);
                }
                float spre = (s0 + s1) + (s2 + s3);
                if (spre > S.thrpre[row]) {
                    float sc = spre * 0.125f;
                    float t = (sc > 0.f) ? sc : expm1f(sc);   // exact CELU
                    unsigned slot = atomicAdd(&S.cnt[row], 1u);
                    if (slot < CAP) {
                        S.cand_t[row*CAP + slot] = t;
                        S.cand_idx[row*CAP + slot] = (unsigned short)(kt*TK + tid);
                    }
                }
            }
        }
        __syncthreads();
    }

    // ================= epilogue: detect + softmax + PV + gate =================
    for (int rr = 0; rr < 8; rr++) {
        int row = warp*8 + rr;
        unsigned c = S.cnt[row];
        bool bad = (c > CAP) || (c == 0);
        float l = 0.f;
        float2 o = make_float2(0.f, 0.f);

        if (!bad) {
            float M = -3e38f;
            for (unsigned k = 0; k < c; k++) M = fmaxf(M, S.cand_t[row*CAP + k]);
            // detection: exact max must be consistent with bf16-predicted max
            if (M < S.Mpre[row]*0.125f - 6.f) bad = true;
            if (!bad) {
                for (unsigned k = 0; k < c; k++) {
                    float w = __expf(S.cand_t[row*CAP + k] - M);
                    int idx = S.cand_idx[row*CAP + k];
                    float2 v = *(const float2*)&g_Vf[((size_t)b*SS + idx)*HH + lane*2];
                    l += w;
                    o.x += w * v.x;
                    o.y += w * v.y;
                }
            }
        }

        if (bad) {
            // ---- exact full-row fallback ----
            float fm = -3e38f, fl = 0.f;
            for (int k = lane; k < SS; k += 32) {
                const float* Kr = &g_Kf[((size_t)b*SS + k)*HH];
                float s = 0.f;
                #pragma unroll 16
                for (int d = 0; d < HH; d++) s = fmaf(S.Qs[d*68 + row], Kr[d], s);
                s *= 0.125f;
                float t = (s > 0.f) ? s : expm1f(s);
                float mn = fmaxf(fm, t);
                fl = fl*__expf(fm - mn) + __expf(t - mn);
                fm = mn;
            }
            #pragma unroll
            for (int off = 16; off; off >>= 1) {
                float om = __shfl_xor_sync(0xffffffffu, fm, off);
                float ol = __shfl_xor_sync(0xffffffffu, fl, off);
                float mn = fmaxf(fm, om);
                fl = fl*__expf(fm - mn) + ol*__expf(om - mn);
                fm = mn;
            }
            S.so[warp*64 + lane] = 0.f;
            S.so[warp*64 + lane + 32] = 0.f;
            __syncwarp();
            for (int k = lane; k < SS; k += 32) {
                const float* Kr = &g_Kf[((size_t)b*SS + k)*HH];
                float s = 0.f;
                #pragma unroll 16
                for (int d = 0; d < HH; d++) s = fmaf(S.Qs[d*68 + row], Kr[d], s);
                s *= 0.125f;
                float t = (s > 0.f) ? s : expm1f(s);
                if (t > fm - 20.f) {
                    float w = __expf(t - fm);
                    const float* Vr = &g_Vf[((size_t)b*SS + k)*HH];
                    for (int h = 0; h < HH; h++)
                        atomicAdd(&S.so[warp*64 + h], w * Vr[h]);
                }
            }
            __syncwarp();
            l = fl;
            o.x = S.so[warp*64 + lane*2];
            o.y = S.so[warp*64 + lane*2 + 1];
        }

        float inv = (l > 0.f) ? (1.f / l) : 0.f;
        float2 gt = *(const float2*)&g_gate[b*HH + lane*2];
        float2 res = make_float2(o.x*inv*gt.x, o.y*inv*gt.y);
        *(float2*)&out[((size_t)b*SS + q0 + row)*HH + lane*2] = res;
    }
}

// ---------------- launch ----------------
extern "C" void kernel_launch(void* const* d_in, const int* in_sizes, int n_in,
                              void* d_out, int out_size) {
    int xi = 0;
    for (int i = 0; i < 4; i++) if (in_sizes[i] == BB*SS*DD) { xi = i; break; }
    const float* ptrs[3];
    int w = 0;
    for (int i = 0; i < 4; i++) if (i != xi) ptrs[w++] = (const float*)d_in[i];
    const float* x  = (const float*)d_in[xi];
    const float* Wq = ptrs[0];
    const float* Wk = ptrs[1];
    const float* Wv = ptrs[2];
    float* out = (float*)d_out;

    cudaFuncSetAttribute(attn_kernel, cudaFuncAttributeMaxDynamicSharedMemorySize,
                         (int)sizeof(Smem));

    qkv_kernel<<<RT/32, 192>>>(x, Wq, Wk, Wv);
    gate_kernel<<<BB*HH, 128>>>();
    attn_kernel<<<BB*(SS/TQ), 256, sizeof(Smem)>>>(out);
}

// round 10
// speedup vs baseline: 151.7423x; 1.3390x over previous
#include <cuda_runtime.h>
#include <cuda_bf16.h>
#include <math.h>
#include <stdint.h>

#define BB 8
#define SS 4096
#define DD 256
#define HH 64
#define RT (BB*SS)
#define TQ 64          // q rows per CTA
#define TK 256         // keys per tile
#define NT (SS/TK)     // 16 tiles
#define CAP 16

// ---------------- scratch ----------------
__device__ float g_Qf[RT*HH];
__device__ float g_Kf[RT*HH];
__device__ float g_Vf[RT*HH];
__device__ __nv_bfloat16 g_Kb[RT*HH];
__device__ float g_gate[BB*HH];

__device__ __forceinline__ unsigned fkey(float f) {
    unsigned u = __float_as_uint(f);
    return u ^ ((unsigned)((int)u >> 31) | 0x80000000u);
}
__device__ __forceinline__ float funkey(unsigned u) {
    u ^= (u & 0x80000000u) ? 0x80000000u : 0xffffffffu;
    return __uint_as_float(u);
}

#define CP16(dst, src)  asm volatile("cp.async.cg.shared.global [%0], [%1], 16;" :: "r"(dst), "l"(src) : "memory")
#define CP_COMMIT()     asm volatile("cp.async.commit_group;" ::: "memory")
#define CP_WAIT0()      asm volatile("cp.async.wait_group 0;" ::: "memory")
#define CP_WAIT1()      asm volatile("cp.async.wait_group 1;" ::: "memory")

__device__ __forceinline__ uint32_t smem_u32(const void* p) {
    uint32_t a;
    asm("{ .reg .u64 t; cvta.to.shared.u64 t, %1; cvt.u32.u64 %0, t; }" : "=r"(a) : "l"(p));
    return a;
}

// ---------------- kernel 1: fused QKV GEMM ----------------
__global__ __launch_bounds__(192) void qkv_kernel(
    const float* __restrict__ x, const float* __restrict__ Wq,
    const float* __restrict__ Wk, const float* __restrict__ Wv)
{
    __shared__ float xs[32][DD];
    int row0 = blockIdx.x * 32;
    int tid = threadIdx.x;
    for (int idx = tid; idx < 32*DD; idx += 192) {
        int r = idx >> 8, k = idx & 255;
        xs[r][k] = x[(size_t)(row0 + r)*DD + k];
    }
    __syncthreads();

    int m = tid >> 6;
    int h = tid & 63;
    const float* W = (m == 0) ? Wq : (m == 1) ? Wk : Wv;
    float* O = (m == 0) ? g_Qf : (m == 1) ? g_Kf : g_Vf;

    float acc[32];
    #pragma unroll
    for (int r = 0; r < 32; r++) acc[r] = 0.f;

    #pragma unroll 4
    for (int k = 0; k < DD; k += 2) {
        float w0 = W[(k+0)*HH + h];
        float w1 = W[(k+1)*HH + h];
        #pragma unroll
        for (int r = 0; r < 32; r++) {
            float2 a = *(const float2*)&xs[r][k];
            acc[r] = fmaf(a.x, w0, fmaf(a.y, w1, acc[r]));
        }
    }
    #pragma unroll
    for (int r = 0; r < 32; r++) {
        float v = acc[r];
        O[(size_t)(row0 + r)*HH + h] = v;
        if (m == 1) g_Kb[(size_t)(row0 + r)*HH + h] = __float2bfloat16(v);
    }
}

// ---------------- kernel 2: gate ----------------
__global__ __launch_bounds__(128) void gate_kernel() {
    int b = blockIdx.x >> 6;
    int h = blockIdx.x & 63;
    float s = 0.f;
    for (int i = threadIdx.x; i < SS; i += 128)
        s += g_Qf[((size_t)b*SS + i)*HH + h];
    __shared__ float red[128];
    red[threadIdx.x] = s;
    __syncthreads();
    for (int off = 64; off; off >>= 1) {
        if (threadIdx.x < off) red[threadIdx.x] += red[threadIdx.x + off];
        __syncthreads();
    }
    if (threadIdx.x == 0)
        g_gate[blockIdx.x] = 1.f / (1.f + expf(-red[0] * (1.f / (float)SS)));
}

// ---------------- kernel 3: two-sweep attention ----------------
struct __align__(16) Smem {
    float Qs[64*64];                    // fp32 Q [row][d]  16384 B
    __nv_bfloat16 Kb[2][256*72];        // bf16 K tiles     73728 B
    unsigned rowtile[64*NT];            // 4096 B
    float Mpre[64];
    float thrpre[64];
    unsigned thrkey[64];
    float cand_t[64*CAP];               // 4096 B
    unsigned short cand_idx[64*CAP];    // 2048 B
    unsigned cnt[64];
    int list[64];
    int nlist;
    int pad_;
    float so[8*64];
};

__global__ __launch_bounds__(256, 2) void attn_kernel(float* __restrict__ out) {
    extern __shared__ Smem smem[];
    Smem& S = smem[0];

    int tid = threadIdx.x;
    int b  = blockIdx.x >> 6;
    int q0 = (blockIdx.x & 63) * TQ;

    for (int i = tid; i < 64*NT; i += 256) S.rowtile[i] = 0u;

    // load Q fp32 row-major
    {
        int row = tid >> 2, qt = (tid & 3) * 16;
        const float* Qr = &g_Qf[((size_t)b*SS + q0 + row)*HH + qt];
        #pragma unroll
        for (int d4 = 0; d4 < 16; d4 += 4)
            *(float4*)&S.Qs[row*64 + qt + d4] = *(const float4*)&Qr[d4];
    }

    // preload K tile 0 (bf16) into buf 0
    uint32_t kb_base = smem_u32(&S.Kb[0][0]);
    {
        const __nv_bfloat16* Ksrc = &g_Kb[((size_t)b*SS)*HH];
        #pragma unroll
        for (int j = 0; j < 8; j++) {
            int ch = tid + j*256;
            int key = ch >> 3, cc = ch & 7;
            CP16(kb_base + key*144 + cc*16, (const void*)(Ksrc + (size_t)key*HH + cc*8));
        }
        CP_COMMIT();
    }
    __syncthreads();

    int warp = tid >> 5, lane = tid & 31;
    int g = lane >> 2, tg = lane & 3;
    int wm = warp >> 1, wn = warp & 1;

    // ---- A-fragments in registers, built once from fp32 Q ----
    uint32_t afr[4][4];
    {
        int r0 = wm*16 + g, r1 = r0 + 8;
        #pragma unroll
        for (int kki = 0; kki < 4; kki++) {
            int c0 = kki*16 + tg*2, c1 = c0 + 8;
            __nv_bfloat162 p;
            p = __floats2bfloat162_rn(S.Qs[r0*64+c0], S.Qs[r0*64+c0+1]); afr[kki][0] = *(uint32_t*)&p;
            p = __floats2bfloat162_rn(S.Qs[r1*64+c0], S.Qs[r1*64+c0+1]); afr[kki][1] = *(uint32_t*)&p;
            p = __floats2bfloat162_rn(S.Qs[r0*64+c1], S.Qs[r0*64+c1+1]); afr[kki][2] = *(uint32_t*)&p;
            p = __floats2bfloat162_rn(S.Qs[r1*64+c1], S.Qs[r1*64+c1+1]); afr[kki][3] = *(uint32_t*)&p;
        }
    }

    // ================= sweep 1: bf16 mma, per-(row,tile) max =================
    int buf = 0;
    for (int kt = 0; kt < NT; kt++) {
        if (kt + 1 < NT) {
            const __nv_bfloat16* Ksrc = &g_Kb[((size_t)b*SS + (kt+1)*TK)*HH];
            uint32_t kb = smem_u32(&S.Kb[buf ^ 1][0]);
            #pragma unroll
            for (int j = 0; j < 8; j++) {
                int ch = tid + j*256;
                int key = ch >> 3, cc = ch & 7;
                CP16(kb + key*144 + cc*16, (const void*)(Ksrc + (size_t)key*HH + cc*8));
            }
            CP_COMMIT();
            CP_WAIT1();
        } else {
            CP_WAIT0();
        }
        __syncthreads();   // K[buf] visible to all warps

        const __nv_bfloat16* KB = &S.Kb[buf][0];
        float acc[16][4];
        #pragma unroll
        for (int ni = 0; ni < 16; ni++)
            #pragma unroll
            for (int e = 0; e < 4; e++) acc[ni][e] = 0.f;

        #pragma unroll
        for (int kki = 0; kki < 4; kki++) {
            int kk = kki*16;
            #pragma unroll
            for (int ni = 0; ni < 16; ni++) {
                int key = wn*128 + ni*8 + g;
                uint32_t b0 = *(const uint32_t*)&KB[key*72 + kk + tg*2];
                uint32_t b1 = *(const uint32_t*)&KB[key*72 + kk + 8 + tg*2];
                asm volatile(
                    "mma.sync.aligned.m16n8k16.row.col.f32.bf16.bf16.f32 "
                    "{%0,%1,%2,%3}, {%4,%5,%6,%7}, {%8,%9}, {%0,%1,%2,%3};"
                    : "+f"(acc[ni][0]), "+f"(acc[ni][1]),
                      "+f"(acc[ni][2]), "+f"(acc[ni][3])
                    : "r"(afr[kki][0]), "r"(afr[kki][1]), "r"(afr[kki][2]), "r"(afr[kki][3]),
                      "r"(b0), "r"(b1));
            }
        }

        // per-row max -> rowtile
        float m0 = -3e38f, m1 = -3e38f;
        #pragma unroll
        for (int ni = 0; ni < 16; ni++) {
            m0 = fmaxf(m0, fmaxf(acc[ni][0], acc[ni][1]));
            m1 = fmaxf(m1, fmaxf(acc[ni][2], acc[ni][3]));
        }
        m0 = fmaxf(m0, __shfl_xor_sync(0xffffffffu, m0, 1));
        m0 = fmaxf(m0, __shfl_xor_sync(0xffffffffu, m0, 2));
        m1 = fmaxf(m1, __shfl_xor_sync(0xffffffffu, m1, 1));
        m1 = fmaxf(m1, __shfl_xor_sync(0xffffffffu, m1, 2));
        if (tg == 0) {
            atomicMax(&S.rowtile[(wm*16 + g    )*NT + kt], fkey(m0));
            atomicMax(&S.rowtile[(wm*16 + g + 8)*NT + kt], fkey(m1));
        }
        __syncthreads();   // done reading K[buf] before refill
        buf ^= 1;
    }

    // thresholds (bf16-mma error margins, pre-scale)
    if (tid < 64) {
        unsigned mk = 0u;
        #pragma unroll
        for (int t = 0; t < NT; t++) mk = max(mk, S.rowtile[tid*NT + t]);
        float Mp = funkey(mk);
        S.Mpre[tid]   = Mp;
        S.thrpre[tid] = Mp - 200.f;
        S.thrkey[tid] = fkey(Mp - 240.f);
        S.cnt[tid] = (Mp < 240.f) ? (CAP + 1000u) : 0u;
    }
    __syncthreads();

    // ================= sweep 2: exact fp32 recompute on qualifying tiles =================
    for (int kt = 0; kt < NT; kt++) {
        if (tid == 0) S.nlist = 0;
        __syncthreads();
        if (tid < 64 && S.rowtile[tid*NT + kt] > S.thrkey[tid])
            S.list[atomicAdd(&S.nlist, 1)] = tid;
        __syncthreads();
        int n = S.nlist;
        if (n > 0) {
            float4 kr[16];
            const float* Kr = &g_Kf[((size_t)b*SS + kt*TK + tid)*HH];
            #pragma unroll
            for (int i = 0; i < 16; i++) kr[i] = *(const float4*)&Kr[i*4];
            for (int j = 0; j < n; j++) {
                int row = S.list[j];
                const float* Q = &S.Qs[row*64];
                float s0 = 0.f, s1 = 0.f, s2 = 0.f, s3 = 0.f;
                #pragma unroll
                for (int i = 0; i < 16; i++) {
                    s0 = fmaf(Q[i*4+0], kr[i].x, s0);
                    s1 = fmaf(Q[i*4+1], kr[i].y, s1);
                    s2 = fmaf(Q[i*4+2], kr[i].z, s2);
                    s3 = fmaf(Q[i*4+3], kr[i].w, s3);
                }
                float spre = (s0 + s1) + (s2 + s3);
                if (spre > S.thrpre[row]) {
                    float sc = spre * 0.125f;
                    float t = (sc > 0.f) ? sc : expm1f(sc);
                    unsigned slot = atomicAdd(&S.cnt[row], 1u);
                    if (slot < CAP) {
                        S.cand_t[row*CAP + slot] = t;
                        S.cand_idx[row*CAP + slot] = (unsigned short)(kt*TK + tid);
                    }
                }
            }
        }
        __syncthreads();
    }

    // ================= epilogue: detect + softmax + PV + gate =================
    for (int rr = 0; rr < 8; rr++) {
        int row = warp*8 + rr;
        unsigned c = S.cnt[row];
        bool bad = (c > CAP) || (c == 0);
        float l = 0.f;
        float2 o = make_float2(0.f, 0.f);

        if (!bad) {
            float M = -3e38f;
            for (unsigned k = 0; k < c; k++) M = fmaxf(M, S.cand_t[row*CAP + k]);
            if (M < S.Mpre[row]*0.125f - 6.f) bad = true;   // consistency check
            if (!bad) {
                for (unsigned k = 0; k < c; k++) {
                    float w = __expf(S.cand_t[row*CAP + k] - M);
                    int idx = S.cand_idx[row*CAP + k];
                    float2 v = *(const float2*)&g_Vf[((size_t)b*SS + idx)*HH + lane*2];
                    l += w;
                    o.x += w * v.x;
                    o.y += w * v.y;
                }
            }
        }

        if (bad) {
            // ---- exact full-row fallback ----
            const float* Q = &S.Qs[row*64];
            float fm = -3e38f, fl = 0.f;
            for (int k = lane; k < SS; k += 32) {
                const float* Kr = &g_Kf[((size_t)b*SS + k)*HH];
                float s = 0.f;
                #pragma unroll 16
                for (int d = 0; d < HH; d++) s = fmaf(Q[d], Kr[d], s);
                s *= 0.125f;
                float t = (s > 0.f) ? s : expm1f(s);
                float mn = fmaxf(fm, t);
                fl = fl*__expf(fm - mn) + __expf(t - mn);
                fm = mn;
            }
            #pragma unroll
            for (int off = 16; off; off >>= 1) {
                float om = __shfl_xor_sync(0xffffffffu, fm, off);
                float ol = __shfl_xor_sync(0xffffffffu, fl, off);
                float mn = fmaxf(fm, om);
                fl = fl*__expf(fm - mn) + ol*__expf(om - mn);
                fm = mn;
            }
            S.so[warp*64 + lane] = 0.f;
            S.so[warp*64 + lane + 32] = 0.f;
            __syncwarp();
            for (int k = lane; k < SS; k += 32) {
                const float* Kr = &g_Kf[((size_t)b*SS + k)*HH];
                float s = 0.f;
                #pragma unroll 16
                for (int d = 0; d < HH; d++) s = fmaf(Q[d], Kr[d], s);
                s *= 0.125f;
                float t = (s > 0.f) ? s : expm1f(s);
                if (t > fm - 20.f) {
                    float w = __expf(t - fm);
                    const float* Vr = &g_Vf[((size_t)b*SS + k)*HH];
                    for (int h = 0; h < HH; h++)
                        atomicAdd(&S.so[warp*64 + h], w * Vr[h]);
                }
            }
            __syncwarp();
            l = fl;
            o.x = S.so[warp*64 + lane*2];
            o.y = S.so[warp*64 + lane*2 + 1];
        }

        float inv = (l > 0.f) ? (1.f / l) : 0.f;
        float2 gt = *(const float2*)&g_gate[b*HH + lane*2];
        float2 res = make_float2(o.x*inv*gt.x, o.y*inv*gt.y);
        *(float2*)&out[((size_t)b*SS + q0 + row)*HH + lane*2] = res;
    }
}

// ---------------- launch ----------------
extern "C" void kernel_launch(void* const* d_in, const int* in_sizes, int n_in,
                              void* d_out, int out_size) {
    int xi = 0;
    for (int i = 0; i < 4; i++) if (in_sizes[i] == BB*SS*DD) { xi = i; break; }
    const float* ptrs[3];
    int w = 0;
    for (int i = 0; i < 4; i++) if (i != xi) ptrs[w++] = (const float*)d_in[i];
    const float* x  = (const float*)d_in[xi];
    const float* Wq = ptrs[0];
    const float* Wk = ptrs[1];
    const float* Wv = ptrs[2];
    float* out = (float*)d_out;

    cudaFuncSetAttribute(attn_kernel, cudaFuncAttributeMaxDynamicSharedMemorySize,
                         (int)sizeof(Smem));

    qkv_kernel<<<RT/32, 192>>>(x, Wq, Wk, Wv);
    gate_kernel<<<BB*HH, 128>>>();
    attn_kernel<<<BB*(SS/TQ), 256, sizeof(Smem)>>>(out);
}